// round 4
// baseline (speedup 1.0000x reference)
#include <cuda_runtime.h>
#include <math.h>

#define Bn 16
#define Nn 4096
#define Cn 512
#define Sn 8
#define Hn 8
#define HDn 64

// Scratch (static __device__ — no allocations).
// g_SA / g_SAS layout: [b][s*N + n'] == [b][n*8 + s2]  (flat reinterpreted "sa")
__device__ __align__(16) float g_SA [Bn*Sn*Nn];
__device__ __align__(16) float g_SAS[Bn*Sn*Nn];
__device__ __align__(16) float g_tok[Bn*Sn*Cn];
__device__ __align__(16) float g_qkv[Bn*Sn*3*Cn];
__device__ __align__(16) float g_asp2[Bn*Sn*Cn];

__device__ __forceinline__ float wredmax(float v){
#pragma unroll
    for (int o = 16; o > 0; o >>= 1) v = fmaxf(v, __shfl_xor_sync(0xffffffffu, v, o));
    return v;
}
__device__ __forceinline__ float wredsum(float v){
#pragma unroll
    for (int o = 16; o > 0; o >>= 1) v += __shfl_xor_sync(0xffffffffu, v, o);
    return v;
}

// ---------------------------------------------------------------------------
// K1a: space_attn GEMM. Block handles 128 rows of one batch.
// Writes raw scores (+bias) to g_SA at flat position b*32768 + n*8 + s2.
// grid = 512 blocks (16 b x 32 row-chunks).
// ---------------------------------------------------------------------------
__global__ __launch_bounds__(256, 2) void k1a_gemm(
    const float* __restrict__ x, const float* __restrict__ w_sum,
    const float* __restrict__ b_sum)
{
    __shared__ __align__(16) float ws[Sn*Cn];   // 16KB
    __shared__ float buf[128*8];                 // 4KB
    const int t = threadIdx.x, lane = t & 31, w = t >> 5;
    const int b = blockIdx.x >> 5, n0 = (blockIdx.x & 31) * 128;

    for (int i = t; i < Sn*Cn; i += 256) ws[i] = w_sum[i];
    float bsl = (lane < 8) ? b_sum[lane] : 0.f;
    __syncthreads();

    const float* xb = x + ((size_t)b*Nn + n0)*Cn;

    for (int g = 0; g < 4; g++) {
        const int base = g*32 + w*4;             // local row, 4 rows per warp
        float4 xv[4][4];
#pragma unroll
        for (int r = 0; r < 4; r++) {
            const float4* xr = (const float4*)(xb + (size_t)(base + r)*Cn);
#pragma unroll
            for (int j = 0; j < 4; j++) xv[r][j] = xr[lane + 32*j];
        }
        float acc[4][8];
#pragma unroll
        for (int r = 0; r < 4; r++)
#pragma unroll
            for (int s2 = 0; s2 < 8; s2++) acc[r][s2] = 0.f;

#pragma unroll
        for (int j = 0; j < 4; j++) {
#pragma unroll
            for (int s2 = 0; s2 < 8; s2++) {
                float4 wv = ((const float4*)(ws + s2*Cn))[lane + 32*j];
#pragma unroll
                for (int r = 0; r < 4; r++) {
                    acc[r][s2] = fmaf(xv[r][j].x, wv.x, acc[r][s2]);
                    acc[r][s2] = fmaf(xv[r][j].y, wv.y, acc[r][s2]);
                    acc[r][s2] = fmaf(xv[r][j].z, wv.z, acc[r][s2]);
                    acc[r][s2] = fmaf(xv[r][j].w, wv.w, acc[r][s2]);
                }
            }
        }
#pragma unroll
        for (int r = 0; r < 4; r++)
#pragma unroll
            for (int s2 = 0; s2 < 8; s2++) {
                float v = wredsum(acc[r][s2]);
                if (lane == s2) buf[(base + r)*8 + s2] = v + bsl;
            }
    }
    __syncthreads();
    float* outp = g_SA + (size_t)b*(Sn*Nn) + (size_t)n0*8;
    for (int i = t; i < 1024; i += 256) outp[i] = buf[i];
}

// ---------------------------------------------------------------------------
// K1b: softmax over each 4096-wide flat sa row. grid = 128 (b*8+s).
// Reads g_SA (L2-resident), writes g_SAS.
// ---------------------------------------------------------------------------
__global__ __launch_bounds__(256) void k1b_softmax()
{
    __shared__ float buf[4096];                  // 16KB
    __shared__ float red[16];
    const int t = threadIdx.x, lane = t & 31, w = t >> 5;
    const size_t base = (size_t)blockIdx.x * Nn;

    const float4* inp = (const float4*)(g_SA + base);
    for (int i = t; i < 1024; i += 256) ((float4*)buf)[i] = inp[i];
    __syncthreads();

    float m = -3.4e38f;
    for (int i = t; i < 4096; i += 256) m = fmaxf(m, buf[i]);
    m = wredmax(m);
    if (!lane) red[w] = m;
    __syncthreads();
    float mf = red[0];
#pragma unroll
    for (int i = 1; i < 8; i++) mf = fmaxf(mf, red[i]);

    float zs = 0.f;
    for (int i = t; i < 4096; i += 256) zs += expf(buf[i] - mf);
    zs = wredsum(zs);
    if (!lane) red[8 + w] = zs;
    __syncthreads();
    float Z = 0.f;
#pragma unroll
    for (int i = 0; i < 8; i++) Z += red[8 + i];
    float invZ = 1.f / Z;

    float* sas = g_SAS + base;
    for (int i = t; i < 4096; i += 256)
        sas[i] = expf(buf[i] - mf) * invZ;
}

// ---------------------------------------------------------------------------
// K3: tokens[b,s,c] = max_n prob[b,s,n] * x_flat[b][c*N + n]
// Block (b, 8 c's); 64 register-resident running maxes per thread.
// __launch_bounds__(256,1): reg cap 255 — guarantees no spill of mx[64].
// ---------------------------------------------------------------------------
__global__ __launch_bounds__(256, 1) void k3_tokens(const float* __restrict__ x)
{
    const int t = threadIdx.x, lane = t & 31, w = t >> 5;
    const int b = blockIdx.y, c0 = blockIdx.x * 8;
    const float* xb = x + (size_t)b*Nn*Cn;       // X2 view: xb[c*N + n]
    const float* pb = g_SAS + (size_t)b*Sn*Nn;

    float mx[64];
#pragma unroll
    for (int k = 0; k < 64; k++) mx[k] = -3.4e38f;

    for (int i = 0; i < 16; i++) {
        int n = t + (i << 8);
        float p[8], xv[8];
#pragma unroll
        for (int s2 = 0; s2 < 8; s2++) p[s2] = pb[(size_t)s2*Nn + n];
#pragma unroll
        for (int c = 0; c < 8; c++) xv[c] = xb[(size_t)(c0 + c)*Nn + n];
#pragma unroll
        for (int c = 0; c < 8; c++)
#pragma unroll
            for (int s2 = 0; s2 < 8; s2++)
                mx[c*8 + s2] = fmaxf(mx[c*8 + s2], p[s2] * xv[c]);
    }
#pragma unroll
    for (int k = 0; k < 64; k++) mx[k] = wredmax(mx[k]);

    __shared__ float red[8][64];
    if (!lane) {
#pragma unroll
        for (int k = 0; k < 64; k++) red[w][k] = mx[k];
    }
    __syncthreads();
    if (t < 64) {
        float v = red[0][t];
#pragma unroll
        for (int w2 = 1; w2 < 8; w2++) v = fmaxf(v, red[w2][t]);
        int c = t >> 3, s2 = t & 7;
        g_tok[((size_t)b*Sn + s2)*Cn + c0 + c] = v;
    }
}

// ---------------------------------------------------------------------------
// K4a: qkv[b,r,j] = sum_k tokens[b,r,k] * w_qkv[j,k]   (j over 3C=1536)
// ---------------------------------------------------------------------------
__global__ __launch_bounds__(256) void k4a_qkv(const float* __restrict__ w_qkv)
{
    __shared__ __align__(16) float tokS[Sn*Cn];  // 16KB
    const int t = threadIdx.x, lane = t & 31, w = t >> 5;
    const int b = blockIdx.y, j0 = blockIdx.x * 128;

    for (int i = t; i < Sn*Cn; i += 256) tokS[i] = g_tok[(size_t)b*Sn*Cn + i];
    __syncthreads();

    for (int cc = 0; cc < 4; cc++) {
        int j = j0 + w*16 + cc*4;
        float acc[4][8];
#pragma unroll
        for (int q = 0; q < 4; q++)
#pragma unroll
            for (int r = 0; r < 8; r++) acc[q][r] = 0.f;

#pragma unroll
        for (int ch = 0; ch < 4; ch++) {
            float4 tv[8];
#pragma unroll
            for (int r = 0; r < 8; r++)
                tv[r] = ((const float4*)(tokS + r*Cn))[lane + 32*ch];
#pragma unroll
            for (int q = 0; q < 4; q++) {
                float4 wv = ((const float4*)(w_qkv + (size_t)(j + q)*Cn))[lane + 32*ch];
#pragma unroll
                for (int r = 0; r < 8; r++) {
                    acc[q][r] = fmaf(wv.x, tv[r].x, acc[q][r]);
                    acc[q][r] = fmaf(wv.y, tv[r].y, acc[q][r]);
                    acc[q][r] = fmaf(wv.z, tv[r].z, acc[q][r]);
                    acc[q][r] = fmaf(wv.w, tv[r].w, acc[q][r]);
                }
            }
        }
#pragma unroll
        for (int q = 0; q < 4; q++)
#pragma unroll
            for (int r = 0; r < 8; r++) {
                float v = wredsum(acc[q][r]);
                if (lane == r)
                    g_qkv[((size_t)b*Sn + r)*(3*Cn) + j + q] = v;
            }
    }
}

// ---------------------------------------------------------------------------
// K4b: per-batch 8x8 attention + cross mixing. grid (16, 2): each block
// handles a 256-wide c-half (4 heads). V-half staged in smem.
// ---------------------------------------------------------------------------
__global__ __launch_bounds__(256) void k4b_attn(const float* __restrict__ w_cross)
{
    __shared__ float sc[256];                    // [h_local][i][j], 4 heads
    __shared__ __align__(16) float vS[8][256];   // v half, 8KB
    __shared__ __align__(16) float aspS[8][256]; // 8KB
    __shared__ float wc[64];
    const int t = threadIdx.x;
    const int b = blockIdx.x, c_base = blockIdx.y * 256;
    const int h_base = c_base >> 6;
    const float* qkvb = g_qkv + (size_t)b*Sn*3*Cn;

    if (t < 64) wc[t] = w_cross[t];

    // stage V half: vS[j][c] = qkv[b][j][1024 + c_base + c]
#pragma unroll
    for (int u = 0; u < 8; u++) {
        int i = t + u*256;
        int j = i >> 8, c = i & 255;
        vS[j][c] = qkvb[j*1536 + 1024 + c_base + c];
    }

    // scores for the 4 heads this block needs: t -> (h_local, i, j)
    {
        int hl = t >> 6, i2 = (t >> 3) & 7, j = t & 7;
        int h = h_base + hl;
        const float4* qp = (const float4*)(qkvb + i2*1536 + h*64);
        const float4* kp = (const float4*)(qkvb + j*1536 + 512 + h*64);
        float a = 0.f;
#pragma unroll
        for (int d = 0; d < 16; d++) {
            float4 qq = qp[d], kk = kp[d];
            a = fmaf(qq.x, kk.x, a); a = fmaf(qq.y, kk.y, a);
            a = fmaf(qq.z, kk.z, a); a = fmaf(qq.w, kk.w, a);
        }
        sc[t] = a * 0.125f;                      // scale = hd^-0.5
    }
    __syncthreads();
    if (t < 32) {                                // softmax over j (8)
        float* row = sc + t*8;
        float m = row[0];
#pragma unroll
        for (int j = 1; j < 8; j++) m = fmaxf(m, row[j]);
        float e[8], zz = 0.f;
#pragma unroll
        for (int j = 0; j < 8; j++) { e[j] = expf(row[j] - m); zz += e[j]; }
        float iz = 1.f / zz;
#pragma unroll
        for (int j = 0; j < 8; j++) row[j] = e[j] * iz;
    }
    __syncthreads();
#pragma unroll
    for (int u = 0; u < 8; u++) {                // asp = attn @ v
        int idx = t + u*256;
        int si = idx >> 8, c = idx & 255, hl = c >> 6;
        float a = 0.f;
#pragma unroll
        for (int j = 0; j < 8; j++)
            a = fmaf(sc[hl*64 + si*8 + j], vS[j][c], a);
        aspS[si][c] = a;
    }
    __syncthreads();
    float* a2o = g_asp2 + (size_t)b*Sn*Cn;
#pragma unroll
    for (int u = 0; u < 8; u++) {                // cross mixing
        int idx = t + u*256;
        int si = idx >> 8, c = idx & 255;
        float o = 0.f;
#pragma unroll
        for (int sp = 0; sp < 8; sp++)
            o = fmaf(wc[si*8 + sp], aspS[sp][c], o);
        a2o[si*512 + c_base + c] = o;
    }
}

// ---------------------------------------------------------------------------
// K5: out[b,n,:] = LN( sum_s sa[b,n,s]*asp2[b,s,:] )*gamma + beta + x[b,n,:]
// Warp per row; 2 rows share each a2 LDS load (halves smem traffic).
// ---------------------------------------------------------------------------
__global__ __launch_bounds__(256) void k5_final(
    const float* __restrict__ x, const float* __restrict__ gamma,
    const float* __restrict__ beta, float* __restrict__ out)
{
    __shared__ __align__(16) float a2[Sn*Cn];    // 16KB
    __shared__ __align__(16) float gS[Cn], bS[Cn];
    const int t = threadIdx.x, lane = t & 31, w = t >> 5;
    const int b = blockIdx.y, n0 = blockIdx.x * 32;

    for (int i = t; i < Sn*Cn; i += 256) a2[i] = g_asp2[(size_t)b*Sn*Cn + i];
    for (int i = t; i < Cn; i += 256) { gS[i] = gamma[i]; bS[i] = beta[i]; }
    __syncthreads();

    const float* sab = g_SA + (size_t)b*Sn*Nn;
    for (int rp = 0; rp < 2; rp++) {
        const int n = n0 + w*4 + rp*2;           // rows n, n+1
        float p0[8], p1[8];
#pragma unroll
        for (int s2 = 0; s2 < 8; s2++) {
            p0[s2] = sab[(size_t)s2*Nn + n];
            p1[s2] = sab[(size_t)s2*Nn + n + 1];
        }

        float4 tv0[4], tv1[4];
        float sum0 = 0.f, sum1 = 0.f;
#pragma unroll
        for (int j = 0; j < 4; j++) {
            float4 v0 = make_float4(0.f,0.f,0.f,0.f);
            float4 v1 = make_float4(0.f,0.f,0.f,0.f);
#pragma unroll
            for (int s2 = 0; s2 < 8; s2++) {
                float4 a = ((const float4*)(a2 + s2*Cn))[lane + 32*j];
                v0.x = fmaf(p0[s2], a.x, v0.x); v1.x = fmaf(p1[s2], a.x, v1.x);
                v0.y = fmaf(p0[s2], a.y, v0.y); v1.y = fmaf(p1[s2], a.y, v1.y);
                v0.z = fmaf(p0[s2], a.z, v0.z); v1.z = fmaf(p1[s2], a.z, v1.z);
                v0.w = fmaf(p0[s2], a.w, v0.w); v1.w = fmaf(p1[s2], a.w, v1.w);
            }
            tv0[j] = v0; tv1[j] = v1;
            sum0 += v0.x + v0.y + v0.z + v0.w;
            sum1 += v1.x + v1.y + v1.z + v1.w;
        }
        sum0 = wredsum(sum0);
        sum1 = wredsum(sum1);
        const float mu0 = sum0 * (1.0f/512.0f), mu1 = sum1 * (1.0f/512.0f);
        float sq0 = 0.f, sq1 = 0.f;
#pragma unroll
        for (int j = 0; j < 4; j++) {
            float d0x = tv0[j].x - mu0, d0y = tv0[j].y - mu0, d0z = tv0[j].z - mu0, d0w = tv0[j].w - mu0;
            sq0 = fmaf(d0x,d0x,sq0); sq0 = fmaf(d0y,d0y,sq0); sq0 = fmaf(d0z,d0z,sq0); sq0 = fmaf(d0w,d0w,sq0);
            float d1x = tv1[j].x - mu1, d1y = tv1[j].y - mu1, d1z = tv1[j].z - mu1, d1w = tv1[j].w - mu1;
            sq1 = fmaf(d1x,d1x,sq1); sq1 = fmaf(d1y,d1y,sq1); sq1 = fmaf(d1z,d1z,sq1); sq1 = fmaf(d1w,d1w,sq1);
        }
        sq0 = wredsum(sq0);
        sq1 = wredsum(sq1);
        const float rs0 = rsqrtf(sq0 * (1.0f/512.0f) + 1e-5f);
        const float rs1 = rsqrtf(sq1 * (1.0f/512.0f) + 1e-5f);

        const float4* xr0 = (const float4*)(x + ((size_t)b*Nn + n)*Cn);
        const float4* xr1 = (const float4*)(x + ((size_t)b*Nn + n + 1)*Cn);
        float4* o0 = (float4*)(out + ((size_t)b*Nn + n)*Cn);
        float4* o1 = (float4*)(out + ((size_t)b*Nn + n + 1)*Cn);
#pragma unroll
        for (int j = 0; j < 4; j++) {
            float4 g4 = ((const float4*)gS)[lane + 32*j];
            float4 b4 = ((const float4*)bS)[lane + 32*j];
            float4 xv0 = xr0[lane + 32*j], xv1 = xr1[lane + 32*j];
            float4 r0, r1;
            r0.x = (tv0[j].x - mu0)*rs0*g4.x + b4.x + xv0.x;
            r0.y = (tv0[j].y - mu0)*rs0*g4.y + b4.y + xv0.y;
            r0.z = (tv0[j].z - mu0)*rs0*g4.z + b4.z + xv0.z;
            r0.w = (tv0[j].w - mu0)*rs0*g4.w + b4.w + xv0.w;
            r1.x = (tv1[j].x - mu1)*rs1*g4.x + b4.x + xv1.x;
            r1.y = (tv1[j].y - mu1)*rs1*g4.y + b4.y + xv1.y;
            r1.z = (tv1[j].z - mu1)*rs1*g4.z + b4.z + xv1.z;
            r1.w = (tv1[j].w - mu1)*rs1*g4.w + b4.w + xv1.w;
            o0[lane + 32*j] = r0;
            o1[lane + 32*j] = r1;
        }
    }
}

// ---------------------------------------------------------------------------
extern "C" void kernel_launch(void* const* d_in, const int* in_sizes, int n_in,
                              void* d_out, int out_size)
{
    const float* x       = (const float*)d_in[0];
    const float* w_sum   = (const float*)d_in[1];
    const float* b_sum   = (const float*)d_in[2];
    const float* w_qkv   = (const float*)d_in[3];
    const float* w_cross = (const float*)d_in[4];
    const float* gamma   = (const float*)d_in[5];
    const float* beta    = (const float*)d_in[6];
    float* out = (float*)d_out;

    k1a_gemm<<<Bn*32, 256>>>(x, w_sum, b_sum);
    k1b_softmax<<<Bn*Sn, 256>>>();
    k3_tokens<<<dim3(Cn/8, Bn), 256>>>(x);
    k4a_qkv<<<dim3(12, Bn), 256>>>(w_qkv);
    k4b_attn<<<dim3(Bn, 2), 256>>>(w_cross);
    k5_final<<<dim3(Nn/32, Bn), 256>>>(x, gamma, beta, out);
}

// round 5
// speedup vs baseline: 1.0431x; 1.0431x over previous
#include <cuda_runtime.h>
#include <math.h>

#define Bn 16
#define Nn 4096
#define Cn 512
#define Sn 8
#define Hn 8
#define HDn 64

// Scratch (static __device__ — no allocations).
// g_SA / g_SAS layout: [b][s*N + n'] == [b][n*8 + s2]  (flat reinterpreted "sa")
__device__ __align__(16) float g_SA [Bn*Sn*Nn];
__device__ __align__(16) float g_SAS[Bn*Sn*Nn];
__device__ __align__(16) float g_tok[Bn*Sn*Cn];
__device__ __align__(16) float g_qkv[Bn*Sn*3*Cn];
__device__ __align__(16) float g_asp2[Bn*Sn*Cn];

__device__ __forceinline__ float wredmax(float v){
#pragma unroll
    for (int o = 16; o > 0; o >>= 1) v = fmaxf(v, __shfl_xor_sync(0xffffffffu, v, o));
    return v;
}
__device__ __forceinline__ float wredsum(float v){
#pragma unroll
    for (int o = 16; o > 0; o >>= 1) v += __shfl_xor_sync(0xffffffffu, v, o);
    return v;
}

// ---------------------------------------------------------------------------
// K1a: space_attn GEMM. Block handles 128 rows of one batch.
// Writes raw scores (+bias) to g_SA at flat position b*32768 + n*8 + s2.
// ---------------------------------------------------------------------------
__global__ __launch_bounds__(256, 2) void k1a_gemm(
    const float* __restrict__ x, const float* __restrict__ w_sum,
    const float* __restrict__ b_sum)
{
    __shared__ __align__(16) float ws[Sn*Cn];   // 16KB
    __shared__ float buf[128*8];                 // 4KB
    const int t = threadIdx.x, lane = t & 31, w = t >> 5;
    const int b = blockIdx.x >> 5, n0 = (blockIdx.x & 31) * 128;

    for (int i = t; i < Sn*Cn; i += 256) ws[i] = w_sum[i];
    float bsl = (lane < 8) ? b_sum[lane] : 0.f;
    __syncthreads();

    const float* xb = x + ((size_t)b*Nn + n0)*Cn;

    for (int g = 0; g < 4; g++) {
        const int base = g*32 + w*4;             // local row, 4 rows per warp
        float4 xv[4][4];
#pragma unroll
        for (int r = 0; r < 4; r++) {
            const float4* xr = (const float4*)(xb + (size_t)(base + r)*Cn);
#pragma unroll
            for (int j = 0; j < 4; j++) xv[r][j] = xr[lane + 32*j];
        }
        float acc[4][8];
#pragma unroll
        for (int r = 0; r < 4; r++)
#pragma unroll
            for (int s2 = 0; s2 < 8; s2++) acc[r][s2] = 0.f;

#pragma unroll
        for (int j = 0; j < 4; j++) {
#pragma unroll
            for (int s2 = 0; s2 < 8; s2++) {
                float4 wv = ((const float4*)(ws + s2*Cn))[lane + 32*j];
#pragma unroll
                for (int r = 0; r < 4; r++) {
                    acc[r][s2] = fmaf(xv[r][j].x, wv.x, acc[r][s2]);
                    acc[r][s2] = fmaf(xv[r][j].y, wv.y, acc[r][s2]);
                    acc[r][s2] = fmaf(xv[r][j].z, wv.z, acc[r][s2]);
                    acc[r][s2] = fmaf(xv[r][j].w, wv.w, acc[r][s2]);
                }
            }
        }
#pragma unroll
        for (int r = 0; r < 4; r++)
#pragma unroll
            for (int s2 = 0; s2 < 8; s2++) {
                float v = wredsum(acc[r][s2]);
                if (lane == s2) buf[(base + r)*8 + s2] = v + bsl;
            }
    }
    __syncthreads();
    float* outp = g_SA + (size_t)b*(Sn*Nn) + (size_t)n0*8;
    for (int i = t; i < 1024; i += 256) outp[i] = buf[i];
}

// ---------------------------------------------------------------------------
// K1b: softmax over each 4096-wide flat sa row. grid = 128 (b*8+s).
// ---------------------------------------------------------------------------
__global__ __launch_bounds__(256) void k1b_softmax()
{
    __shared__ float buf[4096];                  // 16KB
    __shared__ float red[16];
    const int t = threadIdx.x, lane = t & 31, w = t >> 5;
    const size_t base = (size_t)blockIdx.x * Nn;

    const float4* inp = (const float4*)(g_SA + base);
    for (int i = t; i < 1024; i += 256) ((float4*)buf)[i] = inp[i];
    __syncthreads();

    float m = -3.4e38f;
    for (int i = t; i < 4096; i += 256) m = fmaxf(m, buf[i]);
    m = wredmax(m);
    if (!lane) red[w] = m;
    __syncthreads();
    float mf = red[0];
#pragma unroll
    for (int i = 1; i < 8; i++) mf = fmaxf(mf, red[i]);

    float zs = 0.f;
    for (int i = t; i < 4096; i += 256) zs += expf(buf[i] - mf);
    zs = wredsum(zs);
    if (!lane) red[8 + w] = zs;
    __syncthreads();
    float Z = 0.f;
#pragma unroll
    for (int i = 0; i < 8; i++) Z += red[8 + i];
    float invZ = 1.f / Z;

    float* sas = g_SAS + base;
    for (int i = t; i < 4096; i += 256)
        sas[i] = expf(buf[i] - mf) * invZ;
}

// ---------------------------------------------------------------------------
// K3: tokens[b,s,c] = max_n prob[b,s,n] * x_flat[b][c*N + n]
// ---------------------------------------------------------------------------
__global__ __launch_bounds__(256, 1) void k3_tokens(const float* __restrict__ x)
{
    const int t = threadIdx.x, lane = t & 31, w = t >> 5;
    const int b = blockIdx.y, c0 = blockIdx.x * 8;
    const float* xb = x + (size_t)b*Nn*Cn;       // X2 view: xb[c*N + n]
    const float* pb = g_SAS + (size_t)b*Sn*Nn;

    float mx[64];
#pragma unroll
    for (int k = 0; k < 64; k++) mx[k] = -3.4e38f;

    for (int i = 0; i < 16; i++) {
        int n = t + (i << 8);
        float p[8], xv[8];
#pragma unroll
        for (int s2 = 0; s2 < 8; s2++) p[s2] = pb[(size_t)s2*Nn + n];
#pragma unroll
        for (int c = 0; c < 8; c++) xv[c] = xb[(size_t)(c0 + c)*Nn + n];
#pragma unroll
        for (int c = 0; c < 8; c++)
#pragma unroll
            for (int s2 = 0; s2 < 8; s2++)
                mx[c*8 + s2] = fmaxf(mx[c*8 + s2], p[s2] * xv[c]);
    }
#pragma unroll
    for (int k = 0; k < 64; k++) mx[k] = wredmax(mx[k]);

    __shared__ float red[8][64];
    if (!lane) {
#pragma unroll
        for (int k = 0; k < 64; k++) red[w][k] = mx[k];
    }
    __syncthreads();
    if (t < 64) {
        float v = red[0][t];
#pragma unroll
        for (int w2 = 1; w2 < 8; w2++) v = fmaxf(v, red[w2][t]);
        int c = t >> 3, s2 = t & 7;
        g_tok[((size_t)b*Sn + s2)*Cn + c0 + c] = v;
    }
}

// ---------------------------------------------------------------------------
// K4a (REWRITTEN): qkv[b,r,j] = dot(tokens[b,r,:], w_qkv[j,:]).
// Warp handles 4 j's x all 8 r. w_qkv rows preloaded into 64 regs (coalesced,
// L2-hot); tokens float4s streamed from gmem (16KB/batch, L1-hot). No smem,
// no syncs. grid (48, 16) = 768 blocks.
// ---------------------------------------------------------------------------
__global__ __launch_bounds__(256) void k4a_qkv(const float* __restrict__ w_qkv)
{
    const int t = threadIdx.x, lane = t & 31, w = t >> 5;
    const int b = blockIdx.y;
    const int j0 = blockIdx.x * 32 + w * 4;      // 4 consecutive j per warp
    const float* tokb = g_tok + (size_t)b*Sn*Cn;
    float* outb = g_qkv + (size_t)b*Sn*3*Cn;

    float4 wv[4][4];
#pragma unroll
    for (int jj = 0; jj < 4; jj++) {
        const float4* wr = (const float4*)(w_qkv + (size_t)(j0 + jj)*Cn);
#pragma unroll
        for (int m = 0; m < 4; m++) wv[jj][m] = wr[lane + 32*m];
    }

    float acc[4][8];
#pragma unroll
    for (int jj = 0; jj < 4; jj++)
#pragma unroll
        for (int r = 0; r < 8; r++) acc[jj][r] = 0.f;

#pragma unroll
    for (int r = 0; r < 8; r++) {
        const float4* tr = (const float4*)(tokb + r*Cn);
#pragma unroll
        for (int m = 0; m < 4; m++) {
            float4 tv = tr[lane + 32*m];
#pragma unroll
            for (int jj = 0; jj < 4; jj++) {
                acc[jj][r] = fmaf(wv[jj][m].x, tv.x, acc[jj][r]);
                acc[jj][r] = fmaf(wv[jj][m].y, tv.y, acc[jj][r]);
                acc[jj][r] = fmaf(wv[jj][m].z, tv.z, acc[jj][r]);
                acc[jj][r] = fmaf(wv[jj][m].w, tv.w, acc[jj][r]);
            }
        }
    }

#pragma unroll
    for (int jj = 0; jj < 4; jj++)
#pragma unroll
        for (int r = 0; r < 8; r++) {
            float v = wredsum(acc[jj][r]);
            if (lane == r) outb[r*(3*Cn) + j0 + jj] = v;
        }
}

// ---------------------------------------------------------------------------
// K4b: per-batch 8x8 attention + cross mixing. grid (16, 4): each block
// handles a 128-wide c-quarter (2 heads). V-quarter staged in smem.
// ---------------------------------------------------------------------------
__global__ __launch_bounds__(256) void k4b_attn(const float* __restrict__ w_cross)
{
    __shared__ float sc[128];                    // [h_local][i][j], 2 heads
    __shared__ __align__(16) float vS[8][128];   // v quarter, 4KB
    __shared__ __align__(16) float aspS[8][128]; // 4KB
    __shared__ float wc[64];
    const int t = threadIdx.x;
    const int b = blockIdx.x, c_base = blockIdx.y * 128;
    const int h_base = c_base >> 6;              // 2 heads per block
    const float* qkvb = g_qkv + (size_t)b*Sn*3*Cn;

    if (t < 64) wc[t] = w_cross[t];

    // stage V quarter: vS[j][c] = qkv[b][j][1024 + c_base + c]
#pragma unroll
    for (int u = 0; u < 4; u++) {
        int i = t + u*256;
        int j = i >> 7, c = i & 127;
        vS[j][c] = qkvb[j*1536 + 1024 + c_base + c];
    }

    // scores for the 2 heads this block needs: t<128 -> (h_local, i, j)
    if (t < 128) {
        int hl = t >> 6, i2 = (t >> 3) & 7, j = t & 7;
        int h = h_base + hl;
        const float4* qp = (const float4*)(qkvb + i2*1536 + h*64);
        const float4* kp = (const float4*)(qkvb + j*1536 + 512 + h*64);
        float a = 0.f;
#pragma unroll
        for (int d = 0; d < 16; d++) {
            float4 qq = qp[d], kk = kp[d];
            a = fmaf(qq.x, kk.x, a); a = fmaf(qq.y, kk.y, a);
            a = fmaf(qq.z, kk.z, a); a = fmaf(qq.w, kk.w, a);
        }
        sc[t] = a * 0.125f;                      // scale = hd^-0.5
    }
    __syncthreads();
    if (t < 16) {                                // softmax over j (8)
        float* row = sc + t*8;
        float m = row[0];
#pragma unroll
        for (int j = 1; j < 8; j++) m = fmaxf(m, row[j]);
        float e[8], zz = 0.f;
#pragma unroll
        for (int j = 0; j < 8; j++) { e[j] = expf(row[j] - m); zz += e[j]; }
        float iz = 1.f / zz;
#pragma unroll
        for (int j = 0; j < 8; j++) row[j] = e[j] * iz;
    }
    __syncthreads();
#pragma unroll
    for (int u = 0; u < 4; u++) {                // asp = attn @ v
        int idx = t + u*256;
        int si = idx >> 7, c = idx & 127, hl = c >> 6;
        float a = 0.f;
#pragma unroll
        for (int j = 0; j < 8; j++)
            a = fmaf(sc[hl*64 + si*8 + j], vS[j][c], a);
        aspS[si][c] = a;
    }
    __syncthreads();
    float* a2o = g_asp2 + (size_t)b*Sn*Cn;
#pragma unroll
    for (int u = 0; u < 4; u++) {                // cross mixing
        int idx = t + u*256;
        int si = idx >> 7, c = idx & 127;
        float o = 0.f;
#pragma unroll
        for (int sp = 0; sp < 8; sp++)
            o = fmaf(wc[si*8 + sp], aspS[sp][c], o);
        a2o[si*512 + c_base + c] = o;
    }
}

// ---------------------------------------------------------------------------
// K5: out[b,n,:] = LN( sum_s sa[b,n,s]*asp2[b,s,:] )*gamma + beta + x[b,n,:]
// Warp per row; 2 rows share each a2 LDS load.
// ---------------------------------------------------------------------------
__global__ __launch_bounds__(256) void k5_final(
    const float* __restrict__ x, const float* __restrict__ gamma,
    const float* __restrict__ beta, float* __restrict__ out)
{
    __shared__ __align__(16) float a2[Sn*Cn];    // 16KB
    __shared__ __align__(16) float gS[Cn], bS[Cn];
    const int t = threadIdx.x, lane = t & 31, w = t >> 5;
    const int b = blockIdx.y, n0 = blockIdx.x * 32;

    for (int i = t; i < Sn*Cn; i += 256) a2[i] = g_asp2[(size_t)b*Sn*Cn + i];
    for (int i = t; i < Cn; i += 256) { gS[i] = gamma[i]; bS[i] = beta[i]; }
    __syncthreads();

    const float* sab = g_SA + (size_t)b*Sn*Nn;
    for (int rp = 0; rp < 2; rp++) {
        const int n = n0 + w*4 + rp*2;           // rows n, n+1
        float p0[8], p1[8];
#pragma unroll
        for (int s2 = 0; s2 < 8; s2++) {
            p0[s2] = sab[(size_t)s2*Nn + n];
            p1[s2] = sab[(size_t)s2*Nn + n + 1];
        }

        float4 tv0[4], tv1[4];
        float sum0 = 0.f, sum1 = 0.f;
#pragma unroll
        for (int j = 0; j < 4; j++) {
            float4 v0 = make_float4(0.f,0.f,0.f,0.f);
            float4 v1 = make_float4(0.f,0.f,0.f,0.f);
#pragma unroll
            for (int s2 = 0; s2 < 8; s2++) {
                float4 a = ((const float4*)(a2 + s2*Cn))[lane + 32*j];
                v0.x = fmaf(p0[s2], a.x, v0.x); v1.x = fmaf(p1[s2], a.x, v1.x);
                v0.y = fmaf(p0[s2], a.y, v0.y); v1.y = fmaf(p1[s2], a.y, v1.y);
                v0.z = fmaf(p0[s2], a.z, v0.z); v1.z = fmaf(p1[s2], a.z, v1.z);
                v0.w = fmaf(p0[s2], a.w, v0.w); v1.w = fmaf(p1[s2], a.w, v1.w);
            }
            tv0[j] = v0; tv1[j] = v1;
            sum0 += v0.x + v0.y + v0.z + v0.w;
            sum1 += v1.x + v1.y + v1.z + v1.w;
        }
        sum0 = wredsum(sum0);
        sum1 = wredsum(sum1);
        const float mu0 = sum0 * (1.0f/512.0f), mu1 = sum1 * (1.0f/512.0f);
        float sq0 = 0.f, sq1 = 0.f;
#pragma unroll
        for (int j = 0; j < 4; j++) {
            float d0x = tv0[j].x - mu0, d0y = tv0[j].y - mu0, d0z = tv0[j].z - mu0, d0w = tv0[j].w - mu0;
            sq0 = fmaf(d0x,d0x,sq0); sq0 = fmaf(d0y,d0y,sq0); sq0 = fmaf(d0z,d0z,sq0); sq0 = fmaf(d0w,d0w,sq0);
            float d1x = tv1[j].x - mu1, d1y = tv1[j].y - mu1, d1z = tv1[j].z - mu1, d1w = tv1[j].w - mu1;
            sq1 = fmaf(d1x,d1x,sq1); sq1 = fmaf(d1y,d1y,sq1); sq1 = fmaf(d1z,d1z,sq1); sq1 = fmaf(d1w,d1w,sq1);
        }
        sq0 = wredsum(sq0);
        sq1 = wredsum(sq1);
        const float rs0 = rsqrtf(sq0 * (1.0f/512.0f) + 1e-5f);
        const float rs1 = rsqrtf(sq1 * (1.0f/512.0f) + 1e-5f);

        const float4* xr0 = (const float4*)(x + ((size_t)b*Nn + n)*Cn);
        const float4* xr1 = (const float4*)(x + ((size_t)b*Nn + n + 1)*Cn);
        float4* o0 = (float4*)(out + ((size_t)b*Nn + n)*Cn);
        float4* o1 = (float4*)(out + ((size_t)b*Nn + n + 1)*Cn);
#pragma unroll
        for (int j = 0; j < 4; j++) {
            float4 g4 = ((const float4*)gS)[lane + 32*j];
            float4 b4 = ((const float4*)bS)[lane + 32*j];
            float4 xv0 = xr0[lane + 32*j], xv1 = xr1[lane + 32*j];
            float4 r0, r1;
            r0.x = (tv0[j].x - mu0)*rs0*g4.x + b4.x + xv0.x;
            r0.y = (tv0[j].y - mu0)*rs0*g4.y + b4.y + xv0.y;
            r0.z = (tv0[j].z - mu0)*rs0*g4.z + b4.z + xv0.z;
            r0.w = (tv0[j].w - mu0)*rs0*g4.w + b4.w + xv0.w;
            r1.x = (tv1[j].x - mu1)*rs1*g4.x + b4.x + xv1.x;
            r1.y = (tv1[j].y - mu1)*rs1*g4.y + b4.y + xv1.y;
            r1.z = (tv1[j].z - mu1)*rs1*g4.z + b4.z + xv1.z;
            r1.w = (tv1[j].w - mu1)*rs1*g4.w + b4.w + xv1.w;
            o0[lane + 32*j] = r0;
            o1[lane + 32*j] = r1;
        }
    }
}

// ---------------------------------------------------------------------------
extern "C" void kernel_launch(void* const* d_in, const int* in_sizes, int n_in,
                              void* d_out, int out_size)
{
    const float* x       = (const float*)d_in[0];
    const float* w_sum   = (const float*)d_in[1];
    const float* b_sum   = (const float*)d_in[2];
    const float* w_qkv   = (const float*)d_in[3];
    const float* w_cross = (const float*)d_in[4];
    const float* gamma   = (const float*)d_in[5];
    const float* beta    = (const float*)d_in[6];
    float* out = (float*)d_out;

    k1a_gemm<<<Bn*32, 256>>>(x, w_sum, b_sum);
    k1b_softmax<<<Bn*Sn, 256>>>();
    k3_tokens<<<dim3(Cn/8, Bn), 256>>>(x);
    k4a_qkv<<<dim3(48, Bn), 256>>>(w_qkv);
    k4b_attn<<<dim3(Bn, 4), 256>>>(w_cross);
    k5_final<<<dim3(Nn/32, Bn), 256>>>(x, gamma, beta, out);
}

// round 6
// speedup vs baseline: 1.0909x; 1.0459x over previous
#include <cuda_runtime.h>
#include <math.h>

#define Bn 16
#define Nn 4096
#define Cn 512
#define Sn 8
#define Hn 8
#define HDn 64

// Scratch (static __device__ — no allocations).
// g_SA / g_SAS layout: [b][s*N + n'] == [b][n*8 + s2]  (flat reinterpreted "sa")
__device__ __align__(16) float g_SA [Bn*Sn*Nn];
__device__ __align__(16) float g_SAS[Bn*Sn*Nn];
__device__ __align__(16) float g_tok[Bn*Sn*Cn];
__device__ __align__(16) float g_qkv[Bn*Sn*3*Cn];
__device__ __align__(16) float g_asp2[Bn*Sn*Cn];

__device__ __forceinline__ float wredmax(float v){
#pragma unroll
    for (int o = 16; o > 0; o >>= 1) v = fmaxf(v, __shfl_xor_sync(0xffffffffu, v, o));
    return v;
}
__device__ __forceinline__ float wredsum(float v){
#pragma unroll
    for (int o = 16; o > 0; o >>= 1) v += __shfl_xor_sync(0xffffffffu, v, o);
    return v;
}

// ---------------------------------------------------------------------------
// K1a: space_attn GEMM. Block handles 128 rows of one batch.
// ---------------------------------------------------------------------------
__global__ __launch_bounds__(256, 2) void k1a_gemm(
    const float* __restrict__ x, const float* __restrict__ w_sum,
    const float* __restrict__ b_sum)
{
    __shared__ __align__(16) float ws[Sn*Cn];   // 16KB
    __shared__ float buf[128*8];                 // 4KB
    const int t = threadIdx.x, lane = t & 31, w = t >> 5;
    const int b = blockIdx.x >> 5, n0 = (blockIdx.x & 31) * 128;

    for (int i = t; i < Sn*Cn; i += 256) ws[i] = w_sum[i];
    float bsl = (lane < 8) ? b_sum[lane] : 0.f;
    __syncthreads();

    const float* xb = x + ((size_t)b*Nn + n0)*Cn;

    for (int g = 0; g < 4; g++) {
        const int base = g*32 + w*4;             // local row, 4 rows per warp
        float4 xv[4][4];
#pragma unroll
        for (int r = 0; r < 4; r++) {
            const float4* xr = (const float4*)(xb + (size_t)(base + r)*Cn);
#pragma unroll
            for (int j = 0; j < 4; j++) xv[r][j] = xr[lane + 32*j];
        }
        float acc[4][8];
#pragma unroll
        for (int r = 0; r < 4; r++)
#pragma unroll
            for (int s2 = 0; s2 < 8; s2++) acc[r][s2] = 0.f;

#pragma unroll
        for (int j = 0; j < 4; j++) {
#pragma unroll
            for (int s2 = 0; s2 < 8; s2++) {
                float4 wv = ((const float4*)(ws + s2*Cn))[lane + 32*j];
#pragma unroll
                for (int r = 0; r < 4; r++) {
                    acc[r][s2] = fmaf(xv[r][j].x, wv.x, acc[r][s2]);
                    acc[r][s2] = fmaf(xv[r][j].y, wv.y, acc[r][s2]);
                    acc[r][s2] = fmaf(xv[r][j].z, wv.z, acc[r][s2]);
                    acc[r][s2] = fmaf(xv[r][j].w, wv.w, acc[r][s2]);
                }
            }
        }
#pragma unroll
        for (int r = 0; r < 4; r++)
#pragma unroll
            for (int s2 = 0; s2 < 8; s2++) {
                float v = wredsum(acc[r][s2]);
                if (lane == s2) buf[(base + r)*8 + s2] = v + bsl;
            }
    }
    __syncthreads();
    float* outp = g_SA + (size_t)b*(Sn*Nn) + (size_t)n0*8;
    for (int i = t; i < 1024; i += 256) outp[i] = buf[i];
}

// ---------------------------------------------------------------------------
// K1b: softmax over each 4096-wide flat sa row. grid = 128 (b*8+s).
// ---------------------------------------------------------------------------
__global__ __launch_bounds__(256) void k1b_softmax()
{
    __shared__ float buf[4096];                  // 16KB
    __shared__ float red[16];
    const int t = threadIdx.x, lane = t & 31, w = t >> 5;
    const size_t base = (size_t)blockIdx.x * Nn;

    const float4* inp = (const float4*)(g_SA + base);
    for (int i = t; i < 1024; i += 256) ((float4*)buf)[i] = inp[i];
    __syncthreads();

    float m = -3.4e38f;
    for (int i = t; i < 4096; i += 256) m = fmaxf(m, buf[i]);
    m = wredmax(m);
    if (!lane) red[w] = m;
    __syncthreads();
    float mf = red[0];
#pragma unroll
    for (int i = 1; i < 8; i++) mf = fmaxf(mf, red[i]);

    float zs = 0.f;
    for (int i = t; i < 4096; i += 256) zs += expf(buf[i] - mf);
    zs = wredsum(zs);
    if (!lane) red[8 + w] = zs;
    __syncthreads();
    float Z = 0.f;
#pragma unroll
    for (int i = 0; i < 8; i++) Z += red[8 + i];
    float invZ = 1.f / Z;

    float* sas = g_SAS + base;
    for (int i = t; i < 4096; i += 256)
        sas[i] = expf(buf[i] - mf) * invZ;
}

// ---------------------------------------------------------------------------
// K3: tokens[b,s,c] = max_n prob[b,s,n] * x_flat[b][c*N + n]
// c_off selects the c-half (split into 2 launches so ncu's 4th-launch capture
// lands on this kernel next round).
// ---------------------------------------------------------------------------
__global__ __launch_bounds__(256, 1) void k3_tokens(const float* __restrict__ x,
                                                    int c_off)
{
    const int t = threadIdx.x, lane = t & 31, w = t >> 5;
    const int b = blockIdx.y, c0 = c_off + blockIdx.x * 8;
    const float* xb = x + (size_t)b*Nn*Cn;       // X2 view: xb[c*N + n]
    const float* pb = g_SAS + (size_t)b*Sn*Nn;

    float mx[64];
#pragma unroll
    for (int k = 0; k < 64; k++) mx[k] = -3.4e38f;

    for (int i = 0; i < 16; i++) {
        int n = t + (i << 8);
        float p[8], xv[8];
#pragma unroll
        for (int s2 = 0; s2 < 8; s2++) p[s2] = pb[(size_t)s2*Nn + n];
#pragma unroll
        for (int c = 0; c < 8; c++) xv[c] = xb[(size_t)(c0 + c)*Nn + n];
#pragma unroll
        for (int c = 0; c < 8; c++)
#pragma unroll
            for (int s2 = 0; s2 < 8; s2++)
                mx[c*8 + s2] = fmaxf(mx[c*8 + s2], p[s2] * xv[c]);
    }
#pragma unroll
    for (int k = 0; k < 64; k++) mx[k] = wredmax(mx[k]);

    __shared__ float red[8][64];
    if (!lane) {
#pragma unroll
        for (int k = 0; k < 64; k++) red[w][k] = mx[k];
    }
    __syncthreads();
    if (t < 64) {
        float v = red[0][t];
#pragma unroll
        for (int w2 = 1; w2 < 8; w2++) v = fmaxf(v, red[w2][t]);
        int c = t >> 3, s2 = t & 7;
        g_tok[((size_t)b*Sn + s2)*Cn + c0 + c] = v;
    }
}

// ---------------------------------------------------------------------------
// K4a (REWRITE #2): qkv[b,r,j] = dot(tokens[b,r,:], w_qkv[j,:]).
// tokens staged once in smem (padded rows: conflict-free broadcast LDS).
// Thread owns one (j, r) output: 4 interleaved partial accumulators, no
// shuffles, no cross-thread reduction. grid (48, 16); block = 32 j x 8 r.
// ---------------------------------------------------------------------------
#define TPAD 516
__global__ __launch_bounds__(256) void k4a_qkv(const float* __restrict__ w_qkv)
{
    __shared__ __align__(16) float tokS[Sn*TPAD];
    const int t = threadIdx.x;
    const int b = blockIdx.y;
    const int jl = t >> 3, r = t & 7;            // 32 j's x 8 r per block
    const int j = blockIdx.x * 32 + jl;
    const float* tokb = g_tok + (size_t)b*Sn*Cn;

    // stage tokens [8][512] -> padded [8][516]
#pragma unroll
    for (int u = 0; u < 4; u++) {
        int i = t + u*256;                       // i < 1024: (row, 4-chunk)
        int row = i >> 7, ch = i & 127;
        ((float4*)(tokS + row*TPAD))[ch] = ((const float4*)(tokb + row*Cn))[ch];
    }
    __syncthreads();

    const float4* wr = (const float4*)(w_qkv + (size_t)j*Cn);
    const float4* tr = (const float4*)(tokS + r*TPAD);

    float a0 = 0.f, a1 = 0.f, a2 = 0.f, a3 = 0.f;
#pragma unroll 8
    for (int m = 0; m < 128; m += 4) {
        float4 w0 = wr[m+0], w1 = wr[m+1], w2 = wr[m+2], w3 = wr[m+3];
        float4 t0 = tr[m+0], t1 = tr[m+1], t2 = tr[m+2], t3 = tr[m+3];
        a0 = fmaf(w0.x, t0.x, a0); a0 = fmaf(w0.y, t0.y, a0);
        a0 = fmaf(w0.z, t0.z, a0); a0 = fmaf(w0.w, t0.w, a0);
        a1 = fmaf(w1.x, t1.x, a1); a1 = fmaf(w1.y, t1.y, a1);
        a1 = fmaf(w1.z, t1.z, a1); a1 = fmaf(w1.w, t1.w, a1);
        a2 = fmaf(w2.x, t2.x, a2); a2 = fmaf(w2.y, t2.y, a2);
        a2 = fmaf(w2.z, t2.z, a2); a2 = fmaf(w2.w, t2.w, a2);
        a3 = fmaf(w3.x, t3.x, a3); a3 = fmaf(w3.y, t3.y, a3);
        a3 = fmaf(w3.z, t3.z, a3); a3 = fmaf(w3.w, t3.w, a3);
    }
    g_qkv[(size_t)b*Sn*3*Cn + r*(3*Cn) + j] = (a0 + a1) + (a2 + a3);
}

// ---------------------------------------------------------------------------
// K4b: per-batch 8x8 attention + cross mixing. grid (16, 4).
// ---------------------------------------------------------------------------
__global__ __launch_bounds__(256) void k4b_attn(const float* __restrict__ w_cross)
{
    __shared__ float sc[128];                    // [h_local][i][j], 2 heads
    __shared__ __align__(16) float vS[8][128];   // v quarter, 4KB
    __shared__ __align__(16) float aspS[8][128]; // 4KB
    __shared__ float wc[64];
    const int t = threadIdx.x;
    const int b = blockIdx.x, c_base = blockIdx.y * 128;
    const int h_base = c_base >> 6;              // 2 heads per block
    const float* qkvb = g_qkv + (size_t)b*Sn*3*Cn;

    if (t < 64) wc[t] = w_cross[t];

#pragma unroll
    for (int u = 0; u < 4; u++) {
        int i = t + u*256;
        int j = i >> 7, c = i & 127;
        vS[j][c] = qkvb[j*1536 + 1024 + c_base + c];
    }

    if (t < 128) {
        int hl = t >> 6, i2 = (t >> 3) & 7, j = t & 7;
        int h = h_base + hl;
        const float4* qp = (const float4*)(qkvb + i2*1536 + h*64);
        const float4* kp = (const float4*)(qkvb + j*1536 + 512 + h*64);
        float a = 0.f;
#pragma unroll
        for (int d = 0; d < 16; d++) {
            float4 qq = qp[d], kk = kp[d];
            a = fmaf(qq.x, kk.x, a); a = fmaf(qq.y, kk.y, a);
            a = fmaf(qq.z, kk.z, a); a = fmaf(qq.w, kk.w, a);
        }
        sc[t] = a * 0.125f;
    }
    __syncthreads();
    if (t < 16) {                                // softmax over j (8)
        float* row = sc + t*8;
        float m = row[0];
#pragma unroll
        for (int j = 1; j < 8; j++) m = fmaxf(m, row[j]);
        float e[8], zz = 0.f;
#pragma unroll
        for (int j = 0; j < 8; j++) { e[j] = expf(row[j] - m); zz += e[j]; }
        float iz = 1.f / zz;
#pragma unroll
        for (int j = 0; j < 8; j++) row[j] = e[j] * iz;
    }
    __syncthreads();
#pragma unroll
    for (int u = 0; u < 4; u++) {                // asp = attn @ v
        int idx = t + u*256;
        int si = idx >> 7, c = idx & 127, hl = c >> 6;
        float a = 0.f;
#pragma unroll
        for (int j = 0; j < 8; j++)
            a = fmaf(sc[hl*64 + si*8 + j], vS[j][c], a);
        aspS[si][c] = a;
    }
    __syncthreads();
    float* a2o = g_asp2 + (size_t)b*Sn*Cn;
#pragma unroll
    for (int u = 0; u < 4; u++) {                // cross mixing
        int idx = t + u*256;
        int si = idx >> 7, c = idx & 127;
        float o = 0.f;
#pragma unroll
        for (int sp = 0; sp < 8; sp++)
            o = fmaf(wc[si*8 + sp], aspS[sp][c], o);
        a2o[si*512 + c_base + c] = o;
    }
}

// ---------------------------------------------------------------------------
// K5: out[b,n,:] = LN( sum_s sa[b,n,s]*asp2[b,s,:] )*gamma + beta + x[b,n,:]
// 64 rows/block (8 per warp); 2 rows share each a2 LDS load.
// ---------------------------------------------------------------------------
__global__ __launch_bounds__(256) void k5_final(
    const float* __restrict__ x, const float* __restrict__ gamma,
    const float* __restrict__ beta, float* __restrict__ out)
{
    __shared__ __align__(16) float a2[Sn*Cn];    // 16KB
    __shared__ __align__(16) float gS[Cn], bS[Cn];
    const int t = threadIdx.x, lane = t & 31, w = t >> 5;
    const int b = blockIdx.y, n0 = blockIdx.x * 64;

    for (int i = t; i < Sn*Cn; i += 256) a2[i] = g_asp2[(size_t)b*Sn*Cn + i];
    for (int i = t; i < Cn; i += 256) { gS[i] = gamma[i]; bS[i] = beta[i]; }
    __syncthreads();

    const float* sab = g_SA + (size_t)b*Sn*Nn;
    for (int rp = 0; rp < 4; rp++) {
        const int n = n0 + w*8 + rp*2;           // rows n, n+1
        float p0[8], p1[8];
#pragma unroll
        for (int s2 = 0; s2 < 8; s2++) {
            p0[s2] = sab[(size_t)s2*Nn + n];
            p1[s2] = sab[(size_t)s2*Nn + n + 1];
        }

        float4 tv0[4], tv1[4];
        float sum0 = 0.f, sum1 = 0.f;
#pragma unroll
        for (int j = 0; j < 4; j++) {
            float4 v0 = make_float4(0.f,0.f,0.f,0.f);
            float4 v1 = make_float4(0.f,0.f,0.f,0.f);
#pragma unroll
            for (int s2 = 0; s2 < 8; s2++) {
                float4 a = ((const float4*)(a2 + s2*Cn))[lane + 32*j];
                v0.x = fmaf(p0[s2], a.x, v0.x); v1.x = fmaf(p1[s2], a.x, v1.x);
                v0.y = fmaf(p0[s2], a.y, v0.y); v1.y = fmaf(p1[s2], a.y, v1.y);
                v0.z = fmaf(p0[s2], a.z, v0.z); v1.z = fmaf(p1[s2], a.z, v1.z);
                v0.w = fmaf(p0[s2], a.w, v0.w); v1.w = fmaf(p1[s2], a.w, v1.w);
            }
            tv0[j] = v0; tv1[j] = v1;
            sum0 += v0.x + v0.y + v0.z + v0.w;
            sum1 += v1.x + v1.y + v1.z + v1.w;
        }
        sum0 = wredsum(sum0);
        sum1 = wredsum(sum1);
        const float mu0 = sum0 * (1.0f/512.0f), mu1 = sum1 * (1.0f/512.0f);
        float sq0 = 0.f, sq1 = 0.f;
#pragma unroll
        for (int j = 0; j < 4; j++) {
            float d0x = tv0[j].x - mu0, d0y = tv0[j].y - mu0, d0z = tv0[j].z - mu0, d0w = tv0[j].w - mu0;
            sq0 = fmaf(d0x,d0x,sq0); sq0 = fmaf(d0y,d0y,sq0); sq0 = fmaf(d0z,d0z,sq0); sq0 = fmaf(d0w,d0w,sq0);
            float d1x = tv1[j].x - mu1, d1y = tv1[j].y - mu1, d1z = tv1[j].z - mu1, d1w = tv1[j].w - mu1;
            sq1 = fmaf(d1x,d1x,sq1); sq1 = fmaf(d1y,d1y,sq1); sq1 = fmaf(d1z,d1z,sq1); sq1 = fmaf(d1w,d1w,sq1);
        }
        sq0 = wredsum(sq0);
        sq1 = wredsum(sq1);
        const float rs0 = rsqrtf(sq0 * (1.0f/512.0f) + 1e-5f);
        const float rs1 = rsqrtf(sq1 * (1.0f/512.0f) + 1e-5f);

        const float4* xr0 = (const float4*)(x + ((size_t)b*Nn + n)*Cn);
        const float4* xr1 = (const float4*)(x + ((size_t)b*Nn + n + 1)*Cn);
        float4* o0 = (float4*)(out + ((size_t)b*Nn + n)*Cn);
        float4* o1 = (float4*)(out + ((size_t)b*Nn + n + 1)*Cn);
#pragma unroll
        for (int j = 0; j < 4; j++) {
            float4 g4 = ((const float4*)gS)[lane + 32*j];
            float4 b4 = ((const float4*)bS)[lane + 32*j];
            float4 xv0 = xr0[lane + 32*j], xv1 = xr1[lane + 32*j];
            float4 r0, r1;
            r0.x = (tv0[j].x - mu0)*rs0*g4.x + b4.x + xv0.x;
            r0.y = (tv0[j].y - mu0)*rs0*g4.y + b4.y + xv0.y;
            r0.z = (tv0[j].z - mu0)*rs0*g4.z + b4.z + xv0.z;
            r0.w = (tv0[j].w - mu0)*rs0*g4.w + b4.w + xv0.w;
            r1.x = (tv1[j].x - mu1)*rs1*g4.x + b4.x + xv1.x;
            r1.y = (tv1[j].y - mu1)*rs1*g4.y + b4.y + xv1.y;
            r1.z = (tv1[j].z - mu1)*rs1*g4.z + b4.z + xv1.z;
            r1.w = (tv1[j].w - mu1)*rs1*g4.w + b4.w + xv1.w;
            o0[lane + 32*j] = r0;
            o1[lane + 32*j] = r1;
        }
    }
}

// ---------------------------------------------------------------------------
extern "C" void kernel_launch(void* const* d_in, const int* in_sizes, int n_in,
                              void* d_out, int out_size)
{
    const float* x       = (const float*)d_in[0];
    const float* w_sum   = (const float*)d_in[1];
    const float* b_sum   = (const float*)d_in[2];
    const float* w_qkv   = (const float*)d_in[3];
    const float* w_cross = (const float*)d_in[4];
    const float* gamma   = (const float*)d_in[5];
    const float* beta    = (const float*)d_in[6];
    float* out = (float*)d_out;

    k1a_gemm<<<Bn*32, 256>>>(x, w_sum, b_sum);
    k1b_softmax<<<Bn*Sn, 256>>>();
    k3_tokens<<<dim3(32, Bn), 256>>>(x, 0);      // c 0..255   (launch 3)
    k3_tokens<<<dim3(32, Bn), 256>>>(x, 256);    // c 256..511 (launch 4 -> profiled)
    k4a_qkv<<<dim3(48, Bn), 256>>>(w_qkv);
    k4b_attn<<<dim3(Bn, 4), 256>>>(w_cross);
    k5_final<<<dim3(Nn/64, Bn), 256>>>(x, gamma, beta, out);
}

// round 7
// speedup vs baseline: 1.1402x; 1.0452x over previous
#include <cuda_runtime.h>
#include <math.h>

#define Bn 16
#define Nn 4096
#define Cn 512
#define Sn 8
#define Hn 8
#define HDn 64

// Scratch (static __device__ — no allocations).
// g_SA / g_SAS layout: [b][s*N + n'] == [b][n*8 + s2]  (flat reinterpreted "sa")
__device__ __align__(16) float g_SA [Bn*Sn*Nn];
__device__ __align__(16) float g_SAS[Bn*Sn*Nn];
__device__ __align__(16) float g_tok[Bn*Sn*Cn];
__device__ __align__(16) float g_qkv[Bn*Sn*3*Cn];
__device__ __align__(16) float g_asp2[Bn*Sn*Cn];

__device__ __forceinline__ float wredmax(float v){
#pragma unroll
    for (int o = 16; o > 0; o >>= 1) v = fmaxf(v, __shfl_xor_sync(0xffffffffu, v, o));
    return v;
}
__device__ __forceinline__ float wredsum(float v){
#pragma unroll
    for (int o = 16; o > 0; o >>= 1) v += __shfl_xor_sync(0xffffffffu, v, o);
    return v;
}

// ---------------------------------------------------------------------------
// K1a: space_attn GEMM. Block handles 64 rows (2 rows/warp/group, 4 groups).
// grid = 1024 (16 b x 64 row-chunks). Fewer regs -> 3 blocks/SM.
// ---------------------------------------------------------------------------
__global__ __launch_bounds__(256, 3) void k1a_gemm(
    const float* __restrict__ x, const float* __restrict__ w_sum,
    const float* __restrict__ b_sum)
{
    __shared__ __align__(16) float ws[Sn*Cn];   // 16KB
    __shared__ float buf[64*8];                  // 2KB
    const int t = threadIdx.x, lane = t & 31, w = t >> 5;
    const int b = blockIdx.x >> 6, n0 = (blockIdx.x & 63) * 64;

    for (int i = t; i < Sn*Cn; i += 256) ws[i] = w_sum[i];
    float bsl = (lane < 8) ? b_sum[lane] : 0.f;
    __syncthreads();

    const float* xb = x + ((size_t)b*Nn + n0)*Cn;

    for (int g = 0; g < 4; g++) {
        const int base = g*16 + w*2;             // local row, 2 rows per warp
        float4 xv[2][4];
#pragma unroll
        for (int r = 0; r < 2; r++) {
            const float4* xr = (const float4*)(xb + (size_t)(base + r)*Cn);
#pragma unroll
            for (int j = 0; j < 4; j++) xv[r][j] = xr[lane + 32*j];
        }
        float acc[2][8];
#pragma unroll
        for (int r = 0; r < 2; r++)
#pragma unroll
            for (int s2 = 0; s2 < 8; s2++) acc[r][s2] = 0.f;

#pragma unroll
        for (int j = 0; j < 4; j++) {
#pragma unroll
            for (int s2 = 0; s2 < 8; s2++) {
                float4 wv = ((const float4*)(ws + s2*Cn))[lane + 32*j];
#pragma unroll
                for (int r = 0; r < 2; r++) {
                    acc[r][s2] = fmaf(xv[r][j].x, wv.x, acc[r][s2]);
                    acc[r][s2] = fmaf(xv[r][j].y, wv.y, acc[r][s2]);
                    acc[r][s2] = fmaf(xv[r][j].z, wv.z, acc[r][s2]);
                    acc[r][s2] = fmaf(xv[r][j].w, wv.w, acc[r][s2]);
                }
            }
        }
#pragma unroll
        for (int r = 0; r < 2; r++)
#pragma unroll
            for (int s2 = 0; s2 < 8; s2++) {
                float v = wredsum(acc[r][s2]);
                if (lane == s2) buf[(base + r)*8 + s2] = v + bsl;
            }
    }
    __syncthreads();
    float* outp = g_SA + (size_t)b*(Sn*Nn) + (size_t)n0*8;
    for (int i = t; i < 512; i += 256) outp[i] = buf[i];
}

// ---------------------------------------------------------------------------
// K1b: softmax over each 4096-wide flat sa row. grid = 128 (b*8+s).
// ---------------------------------------------------------------------------
__global__ __launch_bounds__(256) void k1b_softmax()
{
    __shared__ float buf[4096];                  // 16KB
    __shared__ float red[16];
    const int t = threadIdx.x, lane = t & 31, w = t >> 5;
    const size_t base = (size_t)blockIdx.x * Nn;

    const float4* inp = (const float4*)(g_SA + base);
    for (int i = t; i < 1024; i += 256) ((float4*)buf)[i] = inp[i];
    __syncthreads();

    float m = -3.4e38f;
    for (int i = t; i < 4096; i += 256) m = fmaxf(m, buf[i]);
    m = wredmax(m);
    if (!lane) red[w] = m;
    __syncthreads();
    float mf = red[0];
#pragma unroll
    for (int i = 1; i < 8; i++) mf = fmaxf(mf, red[i]);

    float zs = 0.f;
    for (int i = t; i < 4096; i += 256) zs += expf(buf[i] - mf);
    zs = wredsum(zs);
    if (!lane) red[8 + w] = zs;
    __syncthreads();
    float Z = 0.f;
#pragma unroll
    for (int i = 0; i < 8; i++) Z += red[8 + i];
    float invZ = 1.f / Z;

    float* sas = g_SAS + base;
    for (int i = t; i < 4096; i += 256)
        sas[i] = expf(buf[i] - mf) * invZ;
}

// ---------------------------------------------------------------------------
// K3 (REDESIGN): tokens[b,s,c] = max_n prob[b,s,n] * x_flat[b][c*N + n]
// 4 c's per block (32 accumulators -> ~2x occupancy). All loads are
// immediate-offset off two advancing base pointers (no per-load IMAD).
// grid (128, 16) = 2048 blocks.
// ---------------------------------------------------------------------------
__global__ __launch_bounds__(256) void k3_tokens(const float* __restrict__ x)
{
    const int t = threadIdx.x, lane = t & 31, w = t >> 5;
    const int b = blockIdx.y, c0 = blockIdx.x * 4;
    const float* xc = x + (size_t)b*Nn*Cn + (size_t)c0*Nn + t;  // X2 view
    const float* pc = g_SAS + (size_t)b*Sn*Nn + t;

    float mx[32];
#pragma unroll
    for (int k = 0; k < 32; k++) mx[k] = -3.4e38f;

#pragma unroll 4
    for (int i = 0; i < 16; i++) {
        float p[8], xv[4];
#pragma unroll
        for (int s2 = 0; s2 < 8; s2++) p[s2] = pc[s2*Nn];   // imm offsets
#pragma unroll
        for (int c = 0; c < 4; c++) xv[c] = xc[c*Nn];       // imm offsets
#pragma unroll
        for (int c = 0; c < 4; c++)
#pragma unroll
            for (int s2 = 0; s2 < 8; s2++)
                mx[c*8 + s2] = fmaxf(mx[c*8 + s2], p[s2] * xv[c]);
        xc += 256; pc += 256;
    }
#pragma unroll
    for (int k = 0; k < 32; k++) mx[k] = wredmax(mx[k]);

    __shared__ float red[8][32];
    if (!lane) {
#pragma unroll
        for (int k = 0; k < 32; k++) red[w][k] = mx[k];
    }
    __syncthreads();
    if (t < 32) {
        float v = red[0][t];
#pragma unroll
        for (int w2 = 1; w2 < 8; w2++) v = fmaxf(v, red[w2][t]);
        int c = t >> 3, s2 = t & 7;
        g_tok[((size_t)b*Sn + s2)*Cn + c0 + c] = v;
    }
}

// ---------------------------------------------------------------------------
// K4a: qkv[b,r,j] = dot(tokens[b,r,:], w_qkv[j,:]).
// tokens staged once in smem (padded rows: conflict-free broadcast LDS).
// Thread owns one (j, r) output. grid (48, 16); block = 32 j x 8 r.
// ---------------------------------------------------------------------------
#define TPAD 516
__global__ __launch_bounds__(256) void k4a_qkv(const float* __restrict__ w_qkv)
{
    __shared__ __align__(16) float tokS[Sn*TPAD];
    const int t = threadIdx.x;
    const int b = blockIdx.y;
    const int jl = t >> 3, r = t & 7;            // 32 j's x 8 r per block
    const int j = blockIdx.x * 32 + jl;
    const float* tokb = g_tok + (size_t)b*Sn*Cn;

#pragma unroll
    for (int u = 0; u < 4; u++) {
        int i = t + u*256;                       // i < 1024: (row, 4-chunk)
        int row = i >> 7, ch = i & 127;
        ((float4*)(tokS + row*TPAD))[ch] = ((const float4*)(tokb + row*Cn))[ch];
    }
    __syncthreads();

    const float4* wr = (const float4*)(w_qkv + (size_t)j*Cn);
    const float4* tr = (const float4*)(tokS + r*TPAD);

    float a0 = 0.f, a1 = 0.f, a2 = 0.f, a3 = 0.f;
#pragma unroll 8
    for (int m = 0; m < 128; m += 4) {
        float4 w0 = wr[m+0], w1 = wr[m+1], w2 = wr[m+2], w3 = wr[m+3];
        float4 t0 = tr[m+0], t1 = tr[m+1], t2 = tr[m+2], t3 = tr[m+3];
        a0 = fmaf(w0.x, t0.x, a0); a0 = fmaf(w0.y, t0.y, a0);
        a0 = fmaf(w0.z, t0.z, a0); a0 = fmaf(w0.w, t0.w, a0);
        a1 = fmaf(w1.x, t1.x, a1); a1 = fmaf(w1.y, t1.y, a1);
        a1 = fmaf(w1.z, t1.z, a1); a1 = fmaf(w1.w, t1.w, a1);
        a2 = fmaf(w2.x, t2.x, a2); a2 = fmaf(w2.y, t2.y, a2);
        a2 = fmaf(w2.z, t2.z, a2); a2 = fmaf(w2.w, t2.w, a2);
        a3 = fmaf(w3.x, t3.x, a3); a3 = fmaf(w3.y, t3.y, a3);
        a3 = fmaf(w3.z, t3.z, a3); a3 = fmaf(w3.w, t3.w, a3);
    }
    g_qkv[(size_t)b*Sn*3*Cn + r*(3*Cn) + j] = (a0 + a1) + (a2 + a3);
}

// ---------------------------------------------------------------------------
// K4b: per-batch 8x8 attention + cross mixing. grid (16, 4).
// ---------------------------------------------------------------------------
__global__ __launch_bounds__(256) void k4b_attn(const float* __restrict__ w_cross)
{
    __shared__ float sc[128];                    // [h_local][i][j], 2 heads
    __shared__ __align__(16) float vS[8][128];   // v quarter, 4KB
    __shared__ __align__(16) float aspS[8][128]; // 4KB
    __shared__ float wc[64];
    const int t = threadIdx.x;
    const int b = blockIdx.x, c_base = blockIdx.y * 128;
    const int h_base = c_base >> 6;              // 2 heads per block
    const float* qkvb = g_qkv + (size_t)b*Sn*3*Cn;

    if (t < 64) wc[t] = w_cross[t];

#pragma unroll
    for (int u = 0; u < 4; u++) {
        int i = t + u*256;
        int j = i >> 7, c = i & 127;
        vS[j][c] = qkvb[j*1536 + 1024 + c_base + c];
    }

    if (t < 128) {
        int hl = t >> 6, i2 = (t >> 3) & 7, j = t & 7;
        int h = h_base + hl;
        const float4* qp = (const float4*)(qkvb + i2*1536 + h*64);
        const float4* kp = (const float4*)(qkvb + j*1536 + 512 + h*64);
        float a = 0.f;
#pragma unroll
        for (int d = 0; d < 16; d++) {
            float4 qq = qp[d], kk = kp[d];
            a = fmaf(qq.x, kk.x, a); a = fmaf(qq.y, kk.y, a);
            a = fmaf(qq.z, kk.z, a); a = fmaf(qq.w, kk.w, a);
        }
        sc[t] = a * 0.125f;
    }
    __syncthreads();
    if (t < 16) {                                // softmax over j (8)
        float* row = sc + t*8;
        float m = row[0];
#pragma unroll
        for (int j = 1; j < 8; j++) m = fmaxf(m, row[j]);
        float e[8], zz = 0.f;
#pragma unroll
        for (int j = 0; j < 8; j++) { e[j] = expf(row[j] - m); zz += e[j]; }
        float iz = 1.f / zz;
#pragma unroll
        for (int j = 0; j < 8; j++) row[j] = e[j] * iz;
    }
    __syncthreads();
#pragma unroll
    for (int u = 0; u < 4; u++) {                // asp = attn @ v
        int idx = t + u*256;
        int si = idx >> 7, c = idx & 127, hl = c >> 6;
        float a = 0.f;
#pragma unroll
        for (int j = 0; j < 8; j++)
            a = fmaf(sc[hl*64 + si*8 + j], vS[j][c], a);
        aspS[si][c] = a;
    }
    __syncthreads();
    float* a2o = g_asp2 + (size_t)b*Sn*Cn;
#pragma unroll
    for (int u = 0; u < 4; u++) {                // cross mixing
        int idx = t + u*256;
        int si = idx >> 7, c = idx & 127;
        float o = 0.f;
#pragma unroll
        for (int sp = 0; sp < 8; sp++)
            o = fmaf(wc[si*8 + sp], aspS[sp][c], o);
        a2o[si*512 + c_base + c] = o;
    }
}

// ---------------------------------------------------------------------------
// K5: out[b,n,:] = LN( sum_s sa[b,n,s]*asp2[b,s,:] )*gamma + beta + x[b,n,:]
// 64 rows/block (8 per warp); 2 rows share each a2 LDS load.
// ---------------------------------------------------------------------------
__global__ __launch_bounds__(256) void k5_final(
    const float* __restrict__ x, const float* __restrict__ gamma,
    const float* __restrict__ beta, float* __restrict__ out)
{
    __shared__ __align__(16) float a2[Sn*Cn];    // 16KB
    __shared__ __align__(16) float gS[Cn], bS[Cn];
    const int t = threadIdx.x, lane = t & 31, w = t >> 5;
    const int b = blockIdx.y, n0 = blockIdx.x * 64;

    for (int i = t; i < Sn*Cn; i += 256) a2[i] = g_asp2[(size_t)b*Sn*Cn + i];
    for (int i = t; i < Cn; i += 256) { gS[i] = gamma[i]; bS[i] = beta[i]; }
    __syncthreads();

    const float* sab = g_SA + (size_t)b*Sn*Nn;
    for (int rp = 0; rp < 4; rp++) {
        const int n = n0 + w*8 + rp*2;           // rows n, n+1
        float p0[8], p1[8];
#pragma unroll
        for (int s2 = 0; s2 < 8; s2++) {
            p0[s2] = sab[(size_t)s2*Nn + n];
            p1[s2] = sab[(size_t)s2*Nn + n + 1];
        }

        float4 tv0[4], tv1[4];
        float sum0 = 0.f, sum1 = 0.f;
#pragma unroll
        for (int j = 0; j < 4; j++) {
            float4 v0 = make_float4(0.f,0.f,0.f,0.f);
            float4 v1 = make_float4(0.f,0.f,0.f,0.f);
#pragma unroll
            for (int s2 = 0; s2 < 8; s2++) {
                float4 a = ((const float4*)(a2 + s2*Cn))[lane + 32*j];
                v0.x = fmaf(p0[s2], a.x, v0.x); v1.x = fmaf(p1[s2], a.x, v1.x);
                v0.y = fmaf(p0[s2], a.y, v0.y); v1.y = fmaf(p1[s2], a.y, v1.y);
                v0.z = fmaf(p0[s2], a.z, v0.z); v1.z = fmaf(p1[s2], a.z, v1.z);
                v0.w = fmaf(p0[s2], a.w, v0.w); v1.w = fmaf(p1[s2], a.w, v1.w);
            }
            tv0[j] = v0; tv1[j] = v1;
            sum0 += v0.x + v0.y + v0.z + v0.w;
            sum1 += v1.x + v1.y + v1.z + v1.w;
        }
        sum0 = wredsum(sum0);
        sum1 = wredsum(sum1);
        const float mu0 = sum0 * (1.0f/512.0f), mu1 = sum1 * (1.0f/512.0f);
        float sq0 = 0.f, sq1 = 0.f;
#pragma unroll
        for (int j = 0; j < 4; j++) {
            float d0x = tv0[j].x - mu0, d0y = tv0[j].y - mu0, d0z = tv0[j].z - mu0, d0w = tv0[j].w - mu0;
            sq0 = fmaf(d0x,d0x,sq0); sq0 = fmaf(d0y,d0y,sq0); sq0 = fmaf(d0z,d0z,sq0); sq0 = fmaf(d0w,d0w,sq0);
            float d1x = tv1[j].x - mu1, d1y = tv1[j].y - mu1, d1z = tv1[j].z - mu1, d1w = tv1[j].w - mu1;
            sq1 = fmaf(d1x,d1x,sq1); sq1 = fmaf(d1y,d1y,sq1); sq1 = fmaf(d1z,d1z,sq1); sq1 = fmaf(d1w,d1w,sq1);
        }
        sq0 = wredsum(sq0);
        sq1 = wredsum(sq1);
        const float rs0 = rsqrtf(sq0 * (1.0f/512.0f) + 1e-5f);
        const float rs1 = rsqrtf(sq1 * (1.0f/512.0f) + 1e-5f);

        const float4* xr0 = (const float4*)(x + ((size_t)b*Nn + n)*Cn);
        const float4* xr1 = (const float4*)(x + ((size_t)b*Nn + n + 1)*Cn);
        float4* o0 = (float4*)(out + ((size_t)b*Nn + n)*Cn);
        float4* o1 = (float4*)(out + ((size_t)b*Nn + n + 1)*Cn);
#pragma unroll
        for (int j = 0; j < 4; j++) {
            float4 g4 = ((const float4*)gS)[lane + 32*j];
            float4 b4 = ((const float4*)bS)[lane + 32*j];
            float4 xv0 = xr0[lane + 32*j], xv1 = xr1[lane + 32*j];
            float4 r0, r1;
            r0.x = (tv0[j].x - mu0)*rs0*g4.x + b4.x + xv0.x;
            r0.y = (tv0[j].y - mu0)*rs0*g4.y + b4.y + xv0.y;
            r0.z = (tv0[j].z - mu0)*rs0*g4.z + b4.z + xv0.z;
            r0.w = (tv0[j].w - mu0)*rs0*g4.w + b4.w + xv0.w;
            r1.x = (tv1[j].x - mu1)*rs1*g4.x + b4.x + xv1.x;
            r1.y = (tv1[j].y - mu1)*rs1*g4.y + b4.y + xv1.y;
            r1.z = (tv1[j].z - mu1)*rs1*g4.z + b4.z + xv1.z;
            r1.w = (tv1[j].w - mu1)*rs1*g4.w + b4.w + xv1.w;
            o0[lane + 32*j] = r0;
            o1[lane + 32*j] = r1;
        }
    }
}

// ---------------------------------------------------------------------------
extern "C" void kernel_launch(void* const* d_in, const int* in_sizes, int n_in,
                              void* d_out, int out_size)
{
    const float* x       = (const float*)d_in[0];
    const float* w_sum   = (const float*)d_in[1];
    const float* b_sum   = (const float*)d_in[2];
    const float* w_qkv   = (const float*)d_in[3];
    const float* w_cross = (const float*)d_in[4];
    const float* gamma   = (const float*)d_in[5];
    const float* beta    = (const float*)d_in[6];
    float* out = (float*)d_out;

    k1a_gemm<<<Bn*64, 256>>>(x, w_sum, b_sum);
    k1b_softmax<<<Bn*Sn, 256>>>();
    k3_tokens<<<dim3(128, Bn), 256>>>(x);
    k4a_qkv<<<dim3(48, Bn), 256>>>(w_qkv);        // launch 4 -> profiled
    k4b_attn<<<dim3(Bn, 4), 256>>>(w_cross);
    k5_final<<<dim3(Nn/64, Bn), 256>>>(x, gamma, beta, out);
}

// round 8
// speedup vs baseline: 1.1786x; 1.0337x over previous
#include <cuda_runtime.h>
#include <math.h>

#define Bn 16
#define Nn 4096
#define Cn 512
#define Sn 8
#define Hn 8
#define HDn 64

// Scratch (static __device__ — no allocations).
// g_SA / g_SAS layout: [b][s*N + n'] == [b][n*8 + s2]  (flat reinterpreted "sa")
__device__ __align__(16) float g_SA [Bn*Sn*Nn];
__device__ __align__(16) float g_SAS[Bn*Sn*Nn];
__device__ __align__(16) float g_tok[Bn*Sn*Cn];
__device__ __align__(16) float g_qkv[Bn*Sn*3*Cn];
__device__ __align__(16) float g_asp2[Bn*Sn*Cn];

__device__ __forceinline__ float wredmax(float v){
#pragma unroll
    for (int o = 16; o > 0; o >>= 1) v = fmaxf(v, __shfl_xor_sync(0xffffffffu, v, o));
    return v;
}
__device__ __forceinline__ float wredsum(float v){
#pragma unroll
    for (int o = 16; o > 0; o >>= 1) v += __shfl_xor_sync(0xffffffffu, v, o);
    return v;
}

// ---------------------------------------------------------------------------
// K1a: space_attn GEMM. Block handles 64 rows (2 rows/warp/group, 4 groups).
// ---------------------------------------------------------------------------
__global__ __launch_bounds__(256, 3) void k1a_gemm(
    const float* __restrict__ x, const float* __restrict__ w_sum,
    const float* __restrict__ b_sum)
{
    __shared__ __align__(16) float ws[Sn*Cn];   // 16KB
    __shared__ float buf[64*8];                  // 2KB
    const int t = threadIdx.x, lane = t & 31, w = t >> 5;
    const int b = blockIdx.x >> 6, n0 = (blockIdx.x & 63) * 64;

    for (int i = t; i < Sn*Cn; i += 256) ws[i] = w_sum[i];
    float bsl = (lane < 8) ? b_sum[lane] : 0.f;
    __syncthreads();

    const float* xb = x + ((size_t)b*Nn + n0)*Cn;

    for (int g = 0; g < 4; g++) {
        const int base = g*16 + w*2;             // local row, 2 rows per warp
        float4 xv[2][4];
#pragma unroll
        for (int r = 0; r < 2; r++) {
            const float4* xr = (const float4*)(xb + (size_t)(base + r)*Cn);
#pragma unroll
            for (int j = 0; j < 4; j++) xv[r][j] = xr[lane + 32*j];
        }
        float acc[2][8];
#pragma unroll
        for (int r = 0; r < 2; r++)
#pragma unroll
            for (int s2 = 0; s2 < 8; s2++) acc[r][s2] = 0.f;

#pragma unroll
        for (int j = 0; j < 4; j++) {
#pragma unroll
            for (int s2 = 0; s2 < 8; s2++) {
                float4 wv = ((const float4*)(ws + s2*Cn))[lane + 32*j];
#pragma unroll
                for (int r = 0; r < 2; r++) {
                    acc[r][s2] = fmaf(xv[r][j].x, wv.x, acc[r][s2]);
                    acc[r][s2] = fmaf(xv[r][j].y, wv.y, acc[r][s2]);
                    acc[r][s2] = fmaf(xv[r][j].z, wv.z, acc[r][s2]);
                    acc[r][s2] = fmaf(xv[r][j].w, wv.w, acc[r][s2]);
                }
            }
        }
#pragma unroll
        for (int r = 0; r < 2; r++)
#pragma unroll
            for (int s2 = 0; s2 < 8; s2++) {
                float v = wredsum(acc[r][s2]);
                if (lane == s2) buf[(base + r)*8 + s2] = v + bsl;
            }
    }
    __syncthreads();
    float* outp = g_SA + (size_t)b*(Sn*Nn) + (size_t)n0*8;
    for (int i = t; i < 512; i += 256) outp[i] = buf[i];
}

// ---------------------------------------------------------------------------
// K1b: softmax over each 4096-wide flat sa row. grid = 128 (b*8+s).
// ---------------------------------------------------------------------------
__global__ __launch_bounds__(256) void k1b_softmax()
{
    __shared__ float buf[4096];                  // 16KB
    __shared__ float red[16];
    const int t = threadIdx.x, lane = t & 31, w = t >> 5;
    const size_t base = (size_t)blockIdx.x * Nn;

    const float4* inp = (const float4*)(g_SA + base);
    for (int i = t; i < 1024; i += 256) ((float4*)buf)[i] = inp[i];
    __syncthreads();

    float m = -3.4e38f;
    for (int i = t; i < 4096; i += 256) m = fmaxf(m, buf[i]);
    m = wredmax(m);
    if (!lane) red[w] = m;
    __syncthreads();
    float mf = red[0];
#pragma unroll
    for (int i = 1; i < 8; i++) mf = fmaxf(mf, red[i]);

    float zs = 0.f;
    for (int i = t; i < 4096; i += 256) zs += expf(buf[i] - mf);
    zs = wredsum(zs);
    if (!lane) red[8 + w] = zs;
    __syncthreads();
    float Z = 0.f;
#pragma unroll
    for (int i = 0; i < 8; i++) Z += red[8 + i];
    float invZ = 1.f / Z;

    float* sas = g_SAS + base;
    for (int i = t; i < 4096; i += 256)
        sas[i] = expf(buf[i] - mf) * invZ;
}

// ---------------------------------------------------------------------------
// K3: tokens[b,s,c] = max_n prob[b,s,n] * x_flat[b][c*N + n]
// 4 c's per block, immediate-offset loads. grid (128, 16).
// ---------------------------------------------------------------------------
__global__ __launch_bounds__(256) void k3_tokens(const float* __restrict__ x)
{
    const int t = threadIdx.x, lane = t & 31, w = t >> 5;
    const int b = blockIdx.y, c0 = blockIdx.x * 4;
    const float* xc = x + (size_t)b*Nn*Cn + (size_t)c0*Nn + t;  // X2 view
    const float* pc = g_SAS + (size_t)b*Sn*Nn + t;

    float mx[32];
#pragma unroll
    for (int k = 0; k < 32; k++) mx[k] = -3.4e38f;

#pragma unroll 4
    for (int i = 0; i < 16; i++) {
        float p[8], xv[4];
#pragma unroll
        for (int s2 = 0; s2 < 8; s2++) p[s2] = pc[s2*Nn];   // imm offsets
#pragma unroll
        for (int c = 0; c < 4; c++) xv[c] = xc[c*Nn];       // imm offsets
#pragma unroll
        for (int c = 0; c < 4; c++)
#pragma unroll
            for (int s2 = 0; s2 < 8; s2++)
                mx[c*8 + s2] = fmaxf(mx[c*8 + s2], p[s2] * xv[c]);
        xc += 256; pc += 256;
    }
#pragma unroll
    for (int k = 0; k < 32; k++) mx[k] = wredmax(mx[k]);

    __shared__ float red[8][32];
    if (!lane) {
#pragma unroll
        for (int k = 0; k < 32; k++) red[w][k] = mx[k];
    }
    __syncthreads();
    if (t < 32) {
        float v = red[0][t];
#pragma unroll
        for (int w2 = 1; w2 < 8; w2++) v = fmaxf(v, red[w2][t]);
        int c = t >> 3, s2 = t & 7;
        g_tok[((size_t)b*Sn + s2)*Cn + c0 + c] = v;
    }
}

// ---------------------------------------------------------------------------
// K4a (REWRITE #3): tiled-smem GEMM. qkv[b,r,j] = dot(tok[b,r,:], w_qkv[j,:]).
// Block = (256-wide j-tile, batch). W chunk [256j x 32k] staged in smem
// (stride 33: conflict-free compute reads); tokens staged once (stride 516).
// Thread computes 4j x 2r register tile: 6 LDS per 8 FMA. grid (6, 16).
// ---------------------------------------------------------------------------
#define TPAD 516
#define WPAD 33
__global__ __launch_bounds__(256) void k4a_qkv(const float* __restrict__ w_qkv)
{
    __shared__ float tokS[Sn*TPAD];              // 16.5KB
    __shared__ float wS[256*WPAD];               // 33.8KB
    const int t = threadIdx.x;
    const int b = blockIdx.y, j0 = blockIdx.x * 256;
    const int jg = t >> 2, rg = t & 3;           // 64 j-groups x 4 r-groups
    const int jb = jg * 4, rb = rg * 2;
    const float* tokb = g_tok + (size_t)b*Sn*Cn;

    // stage tokens [8][512] -> [8][516] (float4 stores, aligned)
#pragma unroll
    for (int u = 0; u < 4; u++) {
        int i = t + u*256;                       // (row, 4-float chunk)
        int row = i >> 7, ch = i & 127;
        ((float4*)(tokS + row*TPAD))[ch] = ((const float4*)(tokb + (size_t)row*Cn))[ch];
    }

    float acc[4][2];
#pragma unroll
    for (int i = 0; i < 4; i++) { acc[i][0] = 0.f; acc[i][1] = 0.f; }

    const int ldrow = t >> 3, ldf4 = t & 7;      // staging map: 32 rows/pass

    for (int kc = 0; kc < 512; kc += 32) {
        __syncthreads();
        // stage W chunk [256][32] -> stride 33, scalar STS (avoids misalign)
#pragma unroll
        for (int p = 0; p < 8; p++) {
            int row = p*32 + ldrow;
            float4 wv = *(const float4*)(w_qkv + (size_t)(j0 + row)*Cn + kc + ldf4*4);
            float* dst = wS + row*WPAD + ldf4*4;
            dst[0] = wv.x; dst[1] = wv.y; dst[2] = wv.z; dst[3] = wv.w;
        }
        __syncthreads();

        const float* tk0 = tokS + rb*TPAD + kc;
        const float* tk1 = tokS + (rb+1)*TPAD + kc;
        const float* wp  = wS + jb*WPAD;
#pragma unroll
        for (int k = 0; k < 32; k++) {
            float t0 = tk0[k], t1 = tk1[k];
            float w0 = wp[0*WPAD + k], w1 = wp[1*WPAD + k];
            float w2 = wp[2*WPAD + k], w3 = wp[3*WPAD + k];
            acc[0][0] = fmaf(w0, t0, acc[0][0]); acc[0][1] = fmaf(w0, t1, acc[0][1]);
            acc[1][0] = fmaf(w1, t0, acc[1][0]); acc[1][1] = fmaf(w1, t1, acc[1][1]);
            acc[2][0] = fmaf(w2, t0, acc[2][0]); acc[2][1] = fmaf(w2, t1, acc[2][1]);
            acc[3][0] = fmaf(w3, t0, acc[3][0]); acc[3][1] = fmaf(w3, t1, acc[3][1]);
        }
    }

    float* outb = g_qkv + (size_t)b*Sn*3*Cn;
#pragma unroll
    for (int i = 0; i < 4; i++) {
        outb[(rb    )*(3*Cn) + j0 + jb + i] = acc[i][0];
        outb[(rb + 1)*(3*Cn) + j0 + jb + i] = acc[i][1];
    }
}

// ---------------------------------------------------------------------------
// K4b: per-batch 8x8 attention + cross mixing. grid (16, 4).
// ---------------------------------------------------------------------------
__global__ __launch_bounds__(256) void k4b_attn(const float* __restrict__ w_cross)
{
    __shared__ float sc[128];                    // [h_local][i][j], 2 heads
    __shared__ __align__(16) float vS[8][128];   // v quarter, 4KB
    __shared__ __align__(16) float aspS[8][128]; // 4KB
    __shared__ float wc[64];
    const int t = threadIdx.x;
    const int b = blockIdx.x, c_base = blockIdx.y * 128;
    const int h_base = c_base >> 6;              // 2 heads per block
    const float* qkvb = g_qkv + (size_t)b*Sn*3*Cn;

    if (t < 64) wc[t] = w_cross[t];

#pragma unroll
    for (int u = 0; u < 4; u++) {
        int i = t + u*256;
        int j = i >> 7, c = i & 127;
        vS[j][c] = qkvb[j*1536 + 1024 + c_base + c];
    }

    if (t < 128) {
        int hl = t >> 6, i2 = (t >> 3) & 7, j = t & 7;
        int h = h_base + hl;
        const float4* qp = (const float4*)(qkvb + i2*1536 + h*64);
        const float4* kp = (const float4*)(qkvb + j*1536 + 512 + h*64);
        float a = 0.f;
#pragma unroll
        for (int d = 0; d < 16; d++) {
            float4 qq = qp[d], kk = kp[d];
            a = fmaf(qq.x, kk.x, a); a = fmaf(qq.y, kk.y, a);
            a = fmaf(qq.z, kk.z, a); a = fmaf(qq.w, kk.w, a);
        }
        sc[t] = a * 0.125f;
    }
    __syncthreads();
    if (t < 16) {                                // softmax over j (8)
        float* row = sc + t*8;
        float m = row[0];
#pragma unroll
        for (int j = 1; j < 8; j++) m = fmaxf(m, row[j]);
        float e[8], zz = 0.f;
#pragma unroll
        for (int j = 0; j < 8; j++) { e[j] = expf(row[j] - m); zz += e[j]; }
        float iz = 1.f / zz;
#pragma unroll
        for (int j = 0; j < 8; j++) row[j] = e[j] * iz;
    }
    __syncthreads();
#pragma unroll
    for (int u = 0; u < 4; u++) {                // asp = attn @ v
        int idx = t + u*256;
        int si = idx >> 7, c = idx & 127, hl = c >> 6;
        float a = 0.f;
#pragma unroll
        for (int j = 0; j < 8; j++)
            a = fmaf(sc[hl*64 + si*8 + j], vS[j][c], a);
        aspS[si][c] = a;
    }
    __syncthreads();
    float* a2o = g_asp2 + (size_t)b*Sn*Cn;
#pragma unroll
    for (int u = 0; u < 4; u++) {                // cross mixing
        int idx = t + u*256;
        int si = idx >> 7, c = idx & 127;
        float o = 0.f;
#pragma unroll
        for (int sp = 0; sp < 8; sp++)
            o = fmaf(wc[si*8 + sp], aspS[sp][c], o);
        a2o[si*512 + c_base + c] = o;
    }
}

// ---------------------------------------------------------------------------
// K5: out[b,n,:] = LN( sum_s sa[b,n,s]*asp2[b,s,:] )*gamma + beta + x[b,n,:]
// 64 rows/block; 4 rows share each a2 LDS.128 (halves smem traffic vs R7).
// ---------------------------------------------------------------------------
__global__ __launch_bounds__(256) void k5_final(
    const float* __restrict__ x, const float* __restrict__ gamma,
    const float* __restrict__ beta, float* __restrict__ out)
{
    __shared__ __align__(16) float a2[Sn*Cn];    // 16KB
    __shared__ __align__(16) float gS[Cn], bS[Cn];
    const int t = threadIdx.x, lane = t & 31, w = t >> 5;
    const int b = blockIdx.y, n0 = blockIdx.x * 64;

    for (int i = t; i < Sn*Cn; i += 256) a2[i] = g_asp2[(size_t)b*Sn*Cn + i];
    for (int i = t; i < Cn; i += 256) { gS[i] = gamma[i]; bS[i] = beta[i]; }
    __syncthreads();

    const float* sab = g_SA + (size_t)b*Sn*Nn;
    for (int rp = 0; rp < 2; rp++) {
        const int n = n0 + w*8 + rp*4;           // rows n..n+3
        float p[4][8];
#pragma unroll
        for (int r = 0; r < 4; r++)
#pragma unroll
            for (int s2 = 0; s2 < 8; s2++)
                p[r][s2] = sab[(size_t)s2*Nn + n + r];

        float4 tv[4][4];
        float sum[4] = {0.f, 0.f, 0.f, 0.f};
#pragma unroll
        for (int j = 0; j < 4; j++) {
            float4 v[4];
#pragma unroll
            for (int r = 0; r < 4; r++) v[r] = make_float4(0.f,0.f,0.f,0.f);
#pragma unroll
            for (int s2 = 0; s2 < 8; s2++) {
                float4 a = ((const float4*)(a2 + s2*Cn))[lane + 32*j];
#pragma unroll
                for (int r = 0; r < 4; r++) {
                    v[r].x = fmaf(p[r][s2], a.x, v[r].x);
                    v[r].y = fmaf(p[r][s2], a.y, v[r].y);
                    v[r].z = fmaf(p[r][s2], a.z, v[r].z);
                    v[r].w = fmaf(p[r][s2], a.w, v[r].w);
                }
            }
#pragma unroll
            for (int r = 0; r < 4; r++) {
                tv[r][j] = v[r];
                sum[r] += v[r].x + v[r].y + v[r].z + v[r].w;
            }
        }
        float mu[4], rs[4];
#pragma unroll
        for (int r = 0; r < 4; r++) {
            sum[r] = wredsum(sum[r]);
            mu[r] = sum[r] * (1.0f/512.0f);
        }
#pragma unroll
        for (int r = 0; r < 4; r++) {
            float sq = 0.f;
#pragma unroll
            for (int j = 0; j < 4; j++) {
                float dx_ = tv[r][j].x - mu[r], dy = tv[r][j].y - mu[r];
                float dz = tv[r][j].z - mu[r], dw = tv[r][j].w - mu[r];
                sq = fmaf(dx_, dx_, sq); sq = fmaf(dy, dy, sq);
                sq = fmaf(dz, dz, sq);   sq = fmaf(dw, dw, sq);
            }
            sq = wredsum(sq);
            rs[r] = rsqrtf(sq * (1.0f/512.0f) + 1e-5f);
        }

#pragma unroll
        for (int r = 0; r < 4; r++) {
            const float4* xr = (const float4*)(x + ((size_t)b*Nn + n + r)*Cn);
            float4* orow = (float4*)(out + ((size_t)b*Nn + n + r)*Cn);
#pragma unroll
            for (int j = 0; j < 4; j++) {
                float4 g4 = ((const float4*)gS)[lane + 32*j];
                float4 b4 = ((const float4*)bS)[lane + 32*j];
                float4 xv = xr[lane + 32*j];
                float4 o;
                o.x = (tv[r][j].x - mu[r])*rs[r]*g4.x + b4.x + xv.x;
                o.y = (tv[r][j].y - mu[r])*rs[r]*g4.y + b4.y + xv.y;
                o.z = (tv[r][j].z - mu[r])*rs[r]*g4.z + b4.z + xv.z;
                o.w = (tv[r][j].w - mu[r])*rs[r]*g4.w + b4.w + xv.w;
                orow[lane + 32*j] = o;
            }
        }
    }
}

// ---------------------------------------------------------------------------
extern "C" void kernel_launch(void* const* d_in, const int* in_sizes, int n_in,
                              void* d_out, int out_size)
{
    const float* x       = (const float*)d_in[0];
    const float* w_sum   = (const float*)d_in[1];
    const float* b_sum   = (const float*)d_in[2];
    const float* w_qkv   = (const float*)d_in[3];
    const float* w_cross = (const float*)d_in[4];
    const float* gamma   = (const float*)d_in[5];
    const float* beta    = (const float*)d_in[6];
    float* out = (float*)d_out;

    k1a_gemm<<<Bn*64, 256>>>(x, w_sum, b_sum);
    k1b_softmax<<<Bn*Sn, 256>>>();
    k3_tokens<<<dim3(128, Bn), 256>>>(x);
    k4a_qkv<<<dim3(6, Bn), 256>>>(w_qkv);         // launch 4 -> profiled
    k4b_attn<<<dim3(Bn, 4), 256>>>(w_cross);
    k5_final<<<dim3(Nn/64, Bn), 256>>>(x, gamma, beta, out);
}